// round 7
// baseline (speedup 1.0000x reference)
#include <cuda_runtime.h>
#include <cstdint>
#include <cstddef>

#define DIM      256
#define KC       1024
#define ROWS     32
#define DK       16
#define NTHREADS 256

typedef unsigned long long ull;

__device__ float g_cnorm[KC];
__device__ float g_partials[4096];

__device__ __forceinline__ void cpa16(void* sdst, const void* gsrc) {
    uint32_t s = (uint32_t)__cvta_generic_to_shared(sdst);
    asm volatile("cp.async.ca.shared.global [%0], [%1], 16;\n" :: "r"(s), "l"(gsrc));
}
__device__ __forceinline__ float frcp(float x) {
    float r; asm("rcp.approx.ftz.f32 %0, %1;" : "=f"(r) : "f"(x)); return r;
}
// Packed fp32x2 FMA (sm_103a FFMA2): acc = a*b + acc, lane-wise, rn semantics.
__device__ __forceinline__ void ffma2(ull& acc, ull a, ull b) {
    asm("fma.rn.f32x2 %0, %1, %2, %0;" : "+l"(acc) : "l"(a), "l"(b));
}
__device__ __forceinline__ ull pack2(float x) {
    ull r; asm("mov.b64 %0, {%1, %1};" : "=l"(r) : "f"(x)); return r;
}
__device__ __forceinline__ float2 unpack2(ull v) {
    float2 r; asm("mov.b64 {%0, %1}, %2;" : "=f"(r.x), "=f"(r.y) : "l"(v)); return r;
}

// ---------------------------------------------------------------- codebook column norms
// 32 blocks x 32 cols; block threads = (dseg 0..7) x (col 0..31); two-level reduce.
__global__ void cnorm_kernel(const float* __restrict__ cb) {
    __shared__ float s[8][32];
    const int c = threadIdx.x & 31, dseg = threadIdx.x >> 5;
    const int col = blockIdx.x * 32 + c;
    float sum = 0.f;
    #pragma unroll
    for (int k = 0; k < 32; ++k) {
        int d = dseg * 32 + k;
        float v = cb[(size_t)d * KC + col];
        sum = fmaf(v, v, sum);
    }
    s[dseg][c] = sum;
    __syncthreads();
    if (threadIdx.x < 32) {
        float t = 0.f;
        #pragma unroll
        for (int i = 0; i < 8; ++i) t += s[i][threadIdx.x];
        g_cnorm[blockIdx.x * 32 + threadIdx.x] = t;
    }
}

// ---------------------------------------------------------------- fused VQ kernel
// CTA: 32 rows x 1024 codes. Thread tile: 4 rows x 32 cols (cols = g*128 + 4*lane + k).
// Accumulators held as fp32x2 pairs: acc[r][2g] = cols (base,base+1), acc[r][2g+1] = (base+2,base+3).
__global__ __launch_bounds__(NTHREADS, 1)
void vq_main(const float* __restrict__ x, const float* __restrict__ cb,
             float* __restrict__ qout, float* __restrict__ scout) {
    extern __shared__ float sm[];
    float* Xs = sm;                 // ROWS*DIM   = 8192 floats
    float* CN = Xs + ROWS * DIM;    // KC         = 1024 floats
    float* Ct = CN + KC;            // 2*DK*KC    = 32768 floats
    __shared__ float wl[8];

    const int tid  = threadIdx.x;
    const int warp = tid >> 5, lane = tid & 31;
    const int row0 = blockIdx.x * ROWS;

    // Load X tile (32 rows x 256 = one contiguous 32KB block)
    {
        const float4* src = (const float4*)(x + (size_t)row0 * DIM);
        float4* dst = (float4*)Xs;
        #pragma unroll
        for (int i = 0; i < 8; ++i) dst[tid + i * NTHREADS] = src[tid + i * NTHREADS];
    }
    __syncthreads();

    // Per-row ||x||^2 (warp w owns rows 4w..4w+3)
    float xn[4];
    #pragma unroll
    for (int r = 0; r < 4; ++r) {
        const float* xr = Xs + (warp * 4 + r) * DIM;
        float s = 0.f;
        #pragma unroll
        for (int i = 0; i < 8; ++i) { float v = xr[lane + 32 * i]; s = fmaf(v, v, s); }
        #pragma unroll
        for (int o = 16; o; o >>= 1) s += __shfl_xor_sync(0xffffffffu, s, o);
        xn[r] = s;
    }

    ull acc[4][16];
    #pragma unroll
    for (int r = 0; r < 4; ++r)
        #pragma unroll
        for (int j = 0; j < 16; ++j) acc[r][j] = 0ull;

    // Prologue: async-load codebook chunk 0
    {
        const float4* src = (const float4*)cb;
        float4* dst = (float4*)Ct;
        #pragma unroll
        for (int i = 0; i < 16; ++i) cpa16(dst + tid + i * NTHREADS, src + tid + i * NTHREADS);
        asm volatile("cp.async.commit_group;\n");
    }

    const int NCHUNK = DIM / DK;   // 16
    for (int c = 0; c < NCHUNK; ++c) {
        if (c + 1 < NCHUNK) {
            const float4* src = (const float4*)(cb + (size_t)(c + 1) * DK * KC);
            float4* dst = (float4*)(Ct + ((c + 1) & 1) * DK * KC);
            #pragma unroll
            for (int i = 0; i < 16; ++i) cpa16(dst + tid + i * NTHREADS, src + tid + i * NTHREADS);
            asm volatile("cp.async.commit_group;\n");
            asm volatile("cp.async.wait_group 1;\n");
        } else {
            asm volatile("cp.async.wait_group 0;\n");
        }
        __syncthreads();

        const float* B  = Ct + (c & 1) * DK * KC;
        const float* Xb = Xs + warp * 4 * DIM + c * DK;
        #pragma unroll 4
        for (int dd = 0; dd < DK; ++dd) {
            ull A0 = pack2(Xb[dd]);
            ull A1 = pack2(Xb[DIM + dd]);
            ull A2 = pack2(Xb[2 * DIM + dd]);
            ull A3 = pack2(Xb[3 * DIM + dd]);
            const ulonglong2* Bd = (const ulonglong2*)(B + dd * KC);
            #pragma unroll
            for (int g = 0; g < 8; ++g) {
                ulonglong2 b = Bd[g * 32 + lane];
                ffma2(acc[0][2 * g], A0, b.x); ffma2(acc[0][2 * g + 1], A0, b.y);
                ffma2(acc[1][2 * g], A1, b.x); ffma2(acc[1][2 * g + 1], A1, b.y);
                ffma2(acc[2][2 * g], A2, b.x); ffma2(acc[2][2 * g + 1], A2, b.y);
                ffma2(acc[3][2 * g], A3, b.x); ffma2(acc[3][2 * g + 1], A3, b.y);
            }
        }
        __syncthreads();
    }

    // Codebook col norms for this lane's columns (loaded late: not needed until epilogue)
    #pragma unroll
    for (int i = 0; i < 4; ++i) CN[tid + i * NTHREADS] = g_cnorm[tid + i * NTHREADS];
    __syncthreads();
    float4 cn4[8];
    #pragma unroll
    for (int g = 0; g < 8; ++g) cn4[g] = ((const float4*)CN)[g * 32 + lane];

    float warploss = 0.f;
    #pragma unroll
    for (int r = 0; r < 4; ++r) {
        const int row = warp * 4 + r;
        const float xnr = xn[r];
        float dmin = 3.4e38f; int didx = 0;
        float4 dv[8];

        // sim -> dist. Ascending col order within lane + strict '<'
        // keeps the lowest tied index (matches jnp.argmin).
        #pragma unroll
        for (int g = 0; g < 8; ++g) {
            float2 p0 = unpack2(acc[r][2 * g]);
            float2 p1 = unpack2(acc[r][2 * g + 1]);
            float4 d4 = make_float4(p0.x, p0.y, p1.x, p1.y);
            float4 c4 = cn4[g];
            int cbse = g * 128 + lane * 4;
            d4.x = fmaf(-2.f, d4.x, xnr + c4.x);
            d4.y = fmaf(-2.f, d4.y, xnr + c4.y);
            d4.z = fmaf(-2.f, d4.z, xnr + c4.z);
            d4.w = fmaf(-2.f, d4.w, xnr + c4.w);
            if (d4.x < dmin) { dmin = d4.x; didx = cbse + 0; }
            if (d4.y < dmin) { dmin = d4.y; didx = cbse + 1; }
            if (d4.z < dmin) { dmin = d4.z; didx = cbse + 2; }
            if (d4.w < dmin) { dmin = d4.w; didx = cbse + 3; }
            dv[g] = d4;
        }

        // Batched reciprocal: 1 MUFU per 8 values, then inv^2, accumulate row sum.
        float lsum = 0.f;
        #pragma unroll
        for (int g = 0; g < 8; g += 2) {
            float4 A = dv[g], B4 = dv[g + 1];
            float pa = A.x * A.y, pb = A.z * A.w, pc = B4.x * B4.y, pd = B4.z * B4.w;
            float pab = pa * pb, pcd = pc * pd;
            float R   = frcp(pab * pcd);
            float rab = pcd * R, rcd = pab * R;          // 1/pab, 1/pcd
            float ra  = pb * rab, rb = pa * rab;          // 1/pa, 1/pb
            float rc_ = pd * rcd, rd = pc * rcd;          // 1/pc, 1/pd
            float i0 = A.y * ra,  i1 = A.x * ra;
            float i2 = A.w * rb,  i3 = A.z * rb;
            float i4 = B4.y * rc_, i5 = B4.x * rc_;
            float i6 = B4.w * rd,  i7 = B4.z * rd;
            i0 *= i0; i1 *= i1; i2 *= i2; i3 *= i3;
            i4 *= i4; i5 *= i5; i6 *= i6; i7 *= i7;
            dv[g]     = make_float4(i0, i1, i2, i3);
            dv[g + 1] = make_float4(i4, i5, i6, i7);
            lsum += ((i0 + i1) + (i2 + i3)) + ((i4 + i5) + (i6 + i7));
        }

        // Warp reductions: row sum + lexicographic (dist, idx) argmin
        #pragma unroll
        for (int o = 16; o; o >>= 1) {
            lsum += __shfl_xor_sync(0xffffffffu, lsum, o);
            float om = __shfl_xor_sync(0xffffffffu, dmin, o);
            int   oi = __shfl_xor_sync(0xffffffffu, didx, o);
            if (om < dmin || (om == dmin && oi < didx)) { dmin = om; didx = oi; }
        }
        const float rS = 1.0f / lsum;

        // Normalized soft counts (coalesced float4 stores)
        float4* srow = (float4*)(scout + (size_t)(row0 + row) * KC);
        #pragma unroll
        for (int g = 0; g < 8; ++g) {
            float4 v = dv[g];
            v.x *= rS; v.y *= rS; v.z *= rS; v.w *= rS;
            srow[g * 32 + lane] = v;
        }

        // Quantized gather (codebook column didx, L2-resident) + loss partial
        const float* xr = Xs + row * DIM;
        float* qr = qout + (size_t)(row0 + row) * DIM;
        float lp = 0.f;
        #pragma unroll
        for (int i = 0; i < 8; ++i) {
            int d = lane + 32 * i;
            float q = cb[(size_t)d * KC + didx];
            qr[d] = q;
            float df = q - xr[d];
            lp = fmaf(df, df, lp);
        }
        warploss += lp;
    }

    #pragma unroll
    for (int o = 16; o; o >>= 1) warploss += __shfl_xor_sync(0xffffffffu, warploss, o);
    if (lane == 0) wl[warp] = warploss;
    __syncthreads();
    if (tid == 0) {
        float t = 0.f;
        #pragma unroll
        for (int i = 0; i < 8; ++i) t += wl[i];
        g_partials[blockIdx.x] = t;
    }
}

// ---------------------------------------------------------------- deterministic loss reduce
__global__ void finalize_kernel(float* __restrict__ lossout, int nparts, float scale) {
    __shared__ float s[256];
    float v = 0.f;
    for (int i = threadIdx.x; i < nparts; i += 256) v += g_partials[i];
    s[threadIdx.x] = v;
    __syncthreads();
    for (int o = 128; o; o >>= 1) {
        if (threadIdx.x < o) s[threadIdx.x] += s[threadIdx.x + o];
        __syncthreads();
    }
    if (threadIdx.x == 0) lossout[0] = s[0] * scale;
}

// ---------------------------------------------------------------- launch
extern "C" void kernel_launch(void* const* d_in, const int* in_sizes, int n_in,
                              void* d_out, int out_size) {
    const float* x  = (const float*)d_in[0];
    const float* cb = (const float*)d_in[1];
    int nx = in_sizes[0], nc = in_sizes[1];
    if (nx < nc) { const float* t = x; x = cb; cb = t; int ti = nx; nx = nc; nc = ti; }

    const int nrows = nx / DIM;              // 65536
    float* out     = (float*)d_out;
    float* qout    = out;                                    // [nrows, 256]
    float* scout   = out + (size_t)nrows * DIM;              // [nrows, 1024]
    float* lossout = scout + (size_t)nrows * KC;             // [1]

    const size_t SMEM = (size_t)(ROWS * DIM + KC + 2 * DK * KC) * sizeof(float);  // 164 KB
    cudaFuncSetAttribute(vq_main, cudaFuncAttributeMaxDynamicSharedMemorySize, (int)SMEM);

    cnorm_kernel<<<32, 256>>>(cb);
    vq_main<<<nrows / ROWS, NTHREADS, SMEM>>>(x, cb, qout, scout);
    finalize_kernel<<<1, 256>>>(lossout, nrows / ROWS, 1.25f / (float)nx);
}

// round 13
// speedup vs baseline: 1.3916x; 1.3916x over previous
#include <cuda_runtime.h>
#include <cuda_fp16.h>
#include <cstdint>
#include <cstddef>

#define DIM  256
#define KC   1024
#define MR   128
#define KP   768          // K' = 3 passes x 256
#define CH   64           // k' rows per chunk
#define NCHG 48           // 4 ntiles x 12 chunks
#define RS_A 520          // halves per A row (512 data + 8 pad)
#define RS_B 72           // halves per B n-row in a chunk (64 data + 8 pad)

// smem byte offsets
#define OFF_A    0                          // 128*520*2 = 133120
#define OFF_B0   133120                     // 256*72*2  = 36864
#define OFF_B1   169984
#define OFF_CN   206848                     // 1024 f
#define OFF_XN   210944                     // 128 f
#define OFF_SS   211456                     // rowsum 128 f
#define OFF_SM1  211968
#define OFF_SM2  212480
#define OFF_SI1  212992
#define OFF_SI2  213504
#define OFF_WL   214016                     // 8 f
#define SMEMSZ   214560

__device__ float  g_cnorm[KC];
__device__ float  g_rowsum[65536];
__device__ float  g_partials[512];
__device__ float  g_cbT[KC * DIM];          // [n][d]
__device__ __half g_bsplit[KC * KP];        // [n][k']: 0-255 Bhi, 256-511 Blo, 512-767 Bhi

__device__ __forceinline__ void cpa16(uint32_t sdst, const void* gsrc) {
    asm volatile("cp.async.ca.shared.global [%0], [%1], 16;\n" :: "r"(sdst), "l"(gsrc));
}
__device__ __forceinline__ float frcp(float x) {
    float r; asm("rcp.approx.ftz.f32 %0, %1;" : "=f"(r) : "f"(x)); return r;
}
__device__ __forceinline__ void mma16816(float* c, uint32_t a0, uint32_t a1, uint32_t a2,
                                         uint32_t a3, uint32_t b0, uint32_t b1) {
    asm volatile(
        "mma.sync.aligned.m16n8k16.row.col.f32.f16.f16.f32 "
        "{%0,%1,%2,%3}, {%4,%5,%6,%7}, {%8,%9}, {%0,%1,%2,%3};"
        : "+f"(c[0]), "+f"(c[1]), "+f"(c[2]), "+f"(c[3])
        : "r"(a0), "r"(a1), "r"(a2), "r"(a3), "r"(b0), "r"(b1));
}
// top-2 merge, both pairs sorted lexicographically by (val, idx)
__device__ __forceinline__ void merge2(float& m1, int& i1, float& m2, int& i2,
                                       float b1, int bi1, float b2, int bi2) {
    if (b1 < m1 || (b1 == m1 && bi1 < i1)) {
        float n2; int nj2;
        if (m1 < b2 || (m1 == b2 && i1 < bi2)) { n2 = m1; nj2 = i1; } else { n2 = b2; nj2 = bi2; }
        m1 = b1; i1 = bi1; m2 = n2; i2 = nj2;
    } else if (b1 < m2 || (b1 == m2 && bi1 < i2)) {
        m2 = b1; i2 = bi1;
    }
}

// ---------------- prep: codebook column norms
__global__ void cnorm_kernel(const float* __restrict__ cb) {
    __shared__ float s[8][32];
    int c = threadIdx.x & 31, ds = threadIdx.x >> 5;
    float sum = 0.f;
    #pragma unroll
    for (int k = 0; k < 32; ++k) {
        float v = cb[(size_t)(ds * 32 + k) * KC + blockIdx.x * 32 + c];
        sum = fmaf(v, v, sum);
    }
    s[ds][c] = sum;
    __syncthreads();
    if (threadIdx.x < 32) {
        float t = 0.f;
        #pragma unroll
        for (int i = 0; i < 8; ++i) t += s[i][threadIdx.x];
        g_cnorm[blockIdx.x * 32 + threadIdx.x] = t;
    }
}

// ---------------- prep: transpose cb -> cbT[n][d]
__global__ void tr_kernel(const float* __restrict__ cb) {
    __shared__ float t[32][33];
    int n0 = blockIdx.x * 32, d0 = blockIdx.y * 32;
    int tx = threadIdx.x, ty = threadIdx.y;
    #pragma unroll
    for (int j = 0; j < 4; ++j) t[ty + j * 8][tx] = cb[(size_t)(d0 + ty + j * 8) * KC + n0 + tx];
    __syncthreads();
    #pragma unroll
    for (int j = 0; j < 4; ++j) g_cbT[(size_t)(n0 + ty + j * 8) * DIM + d0 + tx] = t[tx][ty + j * 8];
}

// ---------------- prep: fp16 split B' [n][k'] n-major
__global__ void split_kernel(const float* __restrict__ cb) {
    int id = blockIdx.x * 256 + threadIdx.x;   // 262144
    int n = id & 1023, k = id >> 10;
    float v = cb[(size_t)k * KC + n];
    __half hi = __float2half_rn(v);
    __half lo = __float2half_rn(v - __half2float(hi));
    size_t base = (size_t)n * KP;
    g_bsplit[base + k] = hi;
    g_bsplit[base + 256 + k] = lo;
    g_bsplit[base + 512 + k] = hi;
}

// ---------------- main fused kernel (grid 512, block 256 = 8 warps)
__global__ __launch_bounds__(256, 1)
void vq_main(const float* __restrict__ x, const float* __restrict__ cb,
             float* __restrict__ qout, float* __restrict__ scout) {
    extern __shared__ char smem[];
    const uint32_t su = (uint32_t)__cvta_generic_to_shared(smem);
    __half* As = (__half*)(smem + OFF_A);
    float* CN = (float*)(smem + OFF_CN);
    float* XN = (float*)(smem + OFF_XN);
    const int tid = threadIdx.x, w = tid >> 5, l = tid & 31;
    const int mw = w & 3, nw = w >> 2;
    const int m0 = mw * 32, ncol0 = nw * 128;
    const int row0 = blockIdx.x * MR;

    // kick B chunk 0 (ntile 0, k' 0..63)
    {
        #pragma unroll
        for (int i = 0; i < 8; ++i) {
            int e = tid + i * 256, n = e >> 3, seg = e & 7;
            cpa16(su + OFF_B0 + (uint32_t)(n * RS_B * 2 + seg * 16),
                  (const char*)g_bsplit + ((size_t)n * KP + seg * 8) * 2);
        }
        asm volatile("cp.async.commit_group;\n");
    }

    // A split: x[128][256] f32 -> As[128][0..255]=hi, [256..511]=lo
    {
        const float4* xs = (const float4*)(x + (size_t)row0 * DIM);
        #pragma unroll
        for (int i = 0; i < 32; ++i) {
            int e = tid + i * 256, row = e >> 6, k4 = (e & 63) * 4;
            float4 v = xs[e];
            __half h0 = __float2half_rn(v.x), h1 = __float2half_rn(v.y);
            __half h2 = __float2half_rn(v.z), h3 = __float2half_rn(v.w);
            __half* ap = As + row * RS_A + k4;
            *(__half2*)(ap)     = __halves2half2(h0, h1);
            *(__half2*)(ap + 2) = __halves2half2(h2, h3);
            *(__half2*)(ap + 256)     = __floats2half2_rn(v.x - __half2float(h0), v.y - __half2float(h1));
            *(__half2*)(ap + 256 + 2) = __floats2half2_rn(v.z - __half2float(h2), v.w - __half2float(h3));
        }
    }
    // XN: warp w -> rows 16w..16w+15
    for (int r = 0; r < 16; ++r) {
        int row = w * 16 + r;
        const float4* xr = (const float4*)(x + (size_t)(row0 + row) * DIM);
        float4 a = xr[l * 2], b = xr[l * 2 + 1];
        float s = a.x * a.x + a.y * a.y + a.z * a.z + a.w * a.w
                + b.x * b.x + b.y * b.y + b.z * b.z + b.w * b.w;
        #pragma unroll
        for (int o = 16; o; o >>= 1) s += __shfl_xor_sync(~0u, s, o);
        if (l == 0) XN[row] = s;
    }
    #pragma unroll
    for (int i = 0; i < 4; ++i) CN[tid + i * 256] = g_cnorm[tid + i * 256];
    __syncthreads();

    float acc[2][16][4];
    float rs[4];  float tm1[4], tm2[4];  int ti1[4], ti2[4];
    #pragma unroll
    for (int q = 0; q < 4; ++q) { rs[q] = 0.f; tm1[q] = 3.4e38f; tm2[q] = 3.4e38f; ti1[q] = 0; ti2[q] = 0; }

    for (int gg = 0; gg < NCHG; ++gg) {
        const int nt = gg / 12, c = gg % 12;
        if (c == 0) {
            #pragma unroll
            for (int mt = 0; mt < 2; ++mt)
                #pragma unroll
                for (int nf = 0; nf < 16; ++nf)
                    #pragma unroll
                    for (int j = 0; j < 4; ++j) acc[mt][nf][j] = 0.f;
        }
        // prefetch gg+1, wait for gg
        if (gg + 1 < NCHG) {
            int nt2 = (gg + 1) / 12, c2 = (gg + 1) % 12;
            uint32_t dbuf = su + (((gg + 1) & 1) ? OFF_B1 : OFF_B0);
            const char* sbase = (const char*)g_bsplit;
            #pragma unroll
            for (int i = 0; i < 8; ++i) {
                int e = tid + i * 256, n = e >> 3, seg = e & 7;
                cpa16(dbuf + (uint32_t)(n * RS_B * 2 + seg * 16),
                      sbase + ((size_t)(nt2 * 256 + n) * KP + c2 * CH + seg * 8) * 2);
            }
            asm volatile("cp.async.commit_group;\n");
            asm volatile("cp.async.wait_group 1;\n");
        } else {
            asm volatile("cp.async.wait_group 0;\n");
        }
        __syncthreads();

        const __half* Bs = (const __half*)(smem + ((gg & 1) ? OFF_B1 : OFF_B0));
        const int acol0 = ((c / 4 == 2) ? 256 : 0) + (c % 4) * CH;
        #pragma unroll
        for (int ks = 0; ks < 4; ++ks) {
            const int ka = acol0 + ks * 16;
            uint32_t a[2][4];
            #pragma unroll
            for (int mt = 0; mt < 2; ++mt) {
                const __half* Ap = As + (m0 + mt * 16 + (l >> 2)) * RS_A + ka + 2 * (l & 3);
                a[mt][0] = *(const uint32_t*)Ap;
                a[mt][1] = *(const uint32_t*)(Ap + 8 * RS_A);
                a[mt][2] = *(const uint32_t*)(Ap + 8);
                a[mt][3] = *(const uint32_t*)(Ap + 8 * RS_A + 8);
            }
            #pragma unroll
            for (int nf = 0; nf < 16; ++nf) {
                // FIX(R11): B rows must include this n-warp's column offset (ncol0).
                const __half* Bp = Bs + (ncol0 + nf * 8 + (l >> 2)) * RS_B + ks * 16 + 2 * (l & 3);
                uint32_t b0 = *(const uint32_t*)Bp;
                uint32_t b1 = *(const uint32_t*)(Bp + 8);
                mma16816(acc[0][nf], a[0][0], a[0][1], a[0][2], a[0][3], b0, b1);
                mma16816(acc[1][nf], a[1][0], a[1][1], a[1][2], a[1][3], b0, b1);
            }
        }
        __syncthreads();

        if (c == 11) {   // ntile nt complete -> epilogue from register fragments
            #pragma unroll
            for (int mt = 0; mt < 2; ++mt)
            #pragma unroll
            for (int t = 0; t < 2; ++t) {
                const int q = mt * 2 + t;
                const int row_l = m0 + mt * 16 + 8 * t + (l >> 2);
                const float xnr = XN[row_l];
                float dd[32];
                float m1 = tm1[q], m2 = tm2[q]; int i1 = ti1[q], i2 = ti2[q];
                #pragma unroll
                for (int nf = 0; nf < 16; ++nf) {
                    int gc = nt * 256 + ncol0 + nf * 8 + 2 * (l & 3);
                    float s0 = acc[mt][nf][t * 2], s1 = acc[mt][nf][t * 2 + 1];
                    float d0 = fmaf(-2.f, s0, xnr + CN[gc]);
                    float d1 = fmaf(-2.f, s1, xnr + CN[gc + 1]);
                    dd[2 * nf] = d0; dd[2 * nf + 1] = d1;
                    if (d0 < m1)      { m2 = m1; i2 = i1; m1 = d0; i1 = gc; }
                    else if (d0 < m2) { m2 = d0; i2 = gc; }
                    if (d1 < m1)      { m2 = m1; i2 = i1; m1 = d1; i1 = gc + 1; }
                    else if (d1 < m2) { m2 = d1; i2 = gc + 1; }
                }
                tm1[q] = m1; tm2[q] = m2; ti1[q] = i1; ti2[q] = i2;
                float Ls = 0.f;
                #pragma unroll
                for (int b = 0; b < 4; ++b) {
                    float* p = dd + b * 8;
                    float pa = p[0] * p[1], pb = p[2] * p[3], pc = p[4] * p[5], pd = p[6] * p[7];
                    float pab = pa * pb, pcd = pc * pd;
                    float R = frcp(pab * pcd);
                    float rab = pcd * R, rcd = pab * R;
                    float ra = pb * rab, rb = pa * rab, rc = pd * rcd, rd = pc * rcd;
                    float v0 = p[1] * ra, v1 = p[0] * ra, v2 = p[3] * rb, v3 = p[2] * rb;
                    float v4 = p[5] * rc, v5 = p[4] * rc, v6 = p[7] * rd, v7 = p[6] * rd;
                    p[0] = v0 * v0; p[1] = v1 * v1; p[2] = v2 * v2; p[3] = v3 * v3;
                    p[4] = v4 * v4; p[5] = v5 * v5; p[6] = v6 * v6; p[7] = v7 * v7;
                    Ls += ((p[0] + p[1]) + (p[2] + p[3])) + ((p[4] + p[5]) + (p[6] + p[7]));
                }
                rs[q] += Ls;
                float* srow = scout + (size_t)(row0 + row_l) * KC;
                #pragma unroll
                for (int nf = 0; nf < 16; ++nf) {
                    int gc = nt * 256 + ncol0 + nf * 8 + 2 * (l & 3);
                    *(float2*)(srow + gc) = make_float2(dd[2 * nf], dd[2 * nf + 1]);
                }
            }
        }
    }

    // ---- combine: quad lanes (same row) then n-warp halves ----
    #pragma unroll
    for (int q = 0; q < 4; ++q) {
        #pragma unroll
        for (int o = 1; o <= 2; o <<= 1) {
            float om1 = __shfl_xor_sync(~0u, tm1[q], o);
            int   oi1 = __shfl_xor_sync(~0u, ti1[q], o);
            float om2 = __shfl_xor_sync(~0u, tm2[q], o);
            int   oi2 = __shfl_xor_sync(~0u, ti2[q], o);
            float ors = __shfl_xor_sync(~0u, rs[q], o);
            rs[q] += ors;
            merge2(tm1[q], ti1[q], tm2[q], ti2[q], om1, oi1, om2, oi2);
        }
    }
    float* sS  = (float*)(smem + OFF_SS);
    float* sM1 = (float*)(smem + OFF_SM1);
    float* sM2 = (float*)(smem + OFF_SM2);
    int*   sI1 = (int*)(smem + OFF_SI1);
    int*   sI2 = (int*)(smem + OFF_SI2);
    __syncthreads();
    if (nw == 1 && (l & 3) == 0) {
        #pragma unroll
        for (int q = 0; q < 4; ++q) {
            int row = m0 + (q >> 1) * 16 + 8 * (q & 1) + (l >> 2);
            sS[row] = rs[q]; sM1[row] = tm1[q]; sI1[row] = ti1[q];
            sM2[row] = tm2[q]; sI2[row] = ti2[q];
        }
    }
    __syncthreads();
    if (nw == 0 && (l & 3) == 0) {
        #pragma unroll
        for (int q = 0; q < 4; ++q) {
            int row = m0 + (q >> 1) * 16 + 8 * (q & 1) + (l >> 2);
            merge2(tm1[q], ti1[q], tm2[q], ti2[q], sM1[row], sI1[row], sM2[row], sI2[row]);
            g_rowsum[row0 + row] = rs[q] + sS[row];
            sI1[row] = ti1[q]; sI2[row] = ti2[q];
        }
    }
    __syncthreads();

    // ---- exact fp32 guard + quantized + loss (8 warps x 16 rows) ----
    float warploss = 0.f;
    for (int rr = 0; rr < 16; ++rr) {
        int lrow = w * 16 + rr, grow = row0 + lrow;
        int i1w = sI1[lrow], i2w = sI2[lrow];
        const float4* xr = (const float4*)(x + (size_t)grow * DIM);
        float4 xa = xr[l * 2], xb = xr[l * 2 + 1];
        const float4* c1p = (const float4*)(g_cbT + (size_t)i1w * DIM);
        const float4* c2p = (const float4*)(g_cbT + (size_t)i2w * DIM);
        float4 ca = c1p[l * 2], cb4 = c1p[l * 2 + 1];
        float4 ea = c2p[l * 2], eb = c2p[l * 2 + 1];
        float d1 = xa.x * ca.x + xa.y * ca.y + xa.z * ca.z + xa.w * ca.w
                 + xb.x * cb4.x + xb.y * cb4.y + xb.z * cb4.z + xb.w * cb4.w;
        float d2 = xa.x * ea.x + xa.y * ea.y + xa.z * ea.z + xa.w * ea.w
                 + xb.x * eb.x + xb.y * eb.y + xb.z * eb.z + xb.w * eb.w;
        #pragma unroll
        for (int o = 16; o; o >>= 1) {
            d1 += __shfl_xor_sync(~0u, d1, o);
            d2 += __shfl_xor_sync(~0u, d2, o);
        }
        float xnr2 = XN[lrow];
        float D1 = fmaf(-2.f, d1, xnr2 + CN[i1w]);
        float D2 = fmaf(-2.f, d2, xnr2 + CN[i2w]);
        float4 qa, qb;
        if ((D2 < D1) || (D2 == D1 && i2w < i1w)) { qa = ea; qb = eb; }
        else { qa = ca; qb = cb4; }
        float4* qp = (float4*)(qout + (size_t)grow * DIM);
        qp[l * 2] = qa; qp[l * 2 + 1] = qb;
        float e0 = qa.x - xa.x, e1 = qa.y - xa.y, e2 = qa.z - xa.z, e3 = qa.w - xa.w;
        float e4 = qb.x - xb.x, e5 = qb.y - xb.y, e6 = qb.z - xb.z, e7 = qb.w - xb.w;
        float lp = ((e0 * e0 + e1 * e1) + (e2 * e2 + e3 * e3))
                 + ((e4 * e4 + e5 * e5) + (e6 * e6 + e7 * e7));
        #pragma unroll
        for (int o = 16; o; o >>= 1) lp += __shfl_xor_sync(~0u, lp, o);
        warploss += lp;
    }
    if (l == 0) ((float*)(smem + OFF_WL))[w] = warploss;
    __syncthreads();
    if (tid == 0) {
        float* wl = (float*)(smem + OFF_WL);
        float t = 0.f;
        #pragma unroll
        for (int i = 0; i < 8; ++i) t += wl[i];
        g_partials[blockIdx.x] = t;
    }
}

// ---------------- normalize soft counts
__global__ void rescale_kernel(float* __restrict__ scout) {
    int row = blockIdx.x;
    float rS = 1.0f / g_rowsum[row];
    float4* p = (float4*)(scout + (size_t)row * KC);
    float4 v = p[threadIdx.x];
    v.x *= rS; v.y *= rS; v.z *= rS; v.w *= rS;
    p[threadIdx.x] = v;
}

// ---------------- loss reduce
__global__ void finalize_kernel(float* __restrict__ lossout, int nparts, float scale) {
    __shared__ float s[256];
    float v = 0.f;
    for (int i = threadIdx.x; i < nparts; i += 256) v += g_partials[i];
    s[threadIdx.x] = v;
    __syncthreads();
    for (int o = 128; o; o >>= 1) {
        if (threadIdx.x < o) s[threadIdx.x] += s[threadIdx.x + o];
        __syncthreads();
    }
    if (threadIdx.x == 0) lossout[0] = s[0] * scale;
}

// ---------------- launch
extern "C" void kernel_launch(void* const* d_in, const int* in_sizes, int n_in,
                              void* d_out, int out_size) {
    const float* x  = (const float*)d_in[0];
    const float* cb = (const float*)d_in[1];
    int nx = in_sizes[0], nc = in_sizes[1];
    if (nx < nc) { const float* t = x; x = cb; cb = t; int ti = nx; nx = nc; nc = ti; }

    const int nrows = nx / DIM;                        // 65536
    float* out     = (float*)d_out;
    float* qout    = out;
    float* scout   = out + (size_t)nrows * DIM;
    float* lossout = scout + (size_t)nrows * KC;

    cudaFuncSetAttribute(vq_main, cudaFuncAttributeMaxDynamicSharedMemorySize, SMEMSZ);

    cnorm_kernel<<<32, 256>>>(cb);
    tr_kernel<<<dim3(32, 8), dim3(32, 8)>>>(cb);
    split_kernel<<<1024, 256>>>(cb);
    vq_main<<<nrows / MR, 256, SMEMSZ>>>(x, cb, qout, scout);
    rescale_kernel<<<nrows, 256>>>(scout);
    finalize_kernel<<<1, 256>>>(lossout, nrows / MR, 1.25f / (float)nx);
}

// round 16
// speedup vs baseline: 1.4540x; 1.0449x over previous
#include <cuda_runtime.h>
#include <cuda_fp16.h>
#include <cstdint>
#include <cstddef>

#define DIM  256
#define KC   1024
#define MR   128
#define KP   768          // K' = 3 passes x 256
#define CH   64           // k' per chunk
#define NCHG 48           // 4 ntiles x 12 chunks
#define RS_A 520          // halves per A row (512 data + 8 pad)
#define RS_B 72           // halves per B n-row (64 data + 8 pad)
#define NT   512          // threads (16 warps)

// smem byte offsets
#define OFF_A    0                     // 128*520*2 = 133120
#define OFF_B0   133120                // 36864
#define OFF_B1   169984                // 36864
#define OFF_CN   206848                // 4096
#define OFF_XN   210944                // 512
#define OFF_SM1  211456                // [4][128] f
#define OFF_SM2  213504
#define OFF_SI1  215552
#define OFF_SI2  217600
#define OFF_SSUM 219648
#define OFF_RCP  221696                // 128 f
#define OFF_FI1  222208                // 128 i
#define OFF_FI2  222720                // 128 i
#define OFF_WL   223232                // 16 f
#define SMEMSZ   223296

__device__ float  g_cnorm[KC];
__device__ float  g_partials[512];
__device__ float  g_cbT[KC * DIM];      // [n][d]
__device__ __half g_bsplit[KC * KP];    // [n][k']: 0-255 Bhi, 256-511 Blo, 512-767 Bhi

__device__ __forceinline__ void cpa16(uint32_t sdst, const void* gsrc) {
    asm volatile("cp.async.ca.shared.global [%0], [%1], 16;\n" :: "r"(sdst), "l"(gsrc));
}
__device__ __forceinline__ float frcp(float x) {
    float r; asm("rcp.approx.ftz.f32 %0, %1;" : "=f"(r) : "f"(x)); return r;
}
__device__ __forceinline__ void ldm4(uint32_t* r, uint32_t addr) {
    asm volatile("ldmatrix.sync.aligned.m8n8.x4.shared.b16 {%0,%1,%2,%3}, [%4];"
        : "=r"(r[0]), "=r"(r[1]), "=r"(r[2]), "=r"(r[3]) : "r"(addr));
}
__device__ __forceinline__ void mma16816(float* c, const uint32_t* a, uint32_t b0, uint32_t b1) {
    asm volatile(
        "mma.sync.aligned.m16n8k16.row.col.f32.f16.f16.f32 "
        "{%0,%1,%2,%3}, {%4,%5,%6,%7}, {%8,%9}, {%0,%1,%2,%3};"
        : "+f"(c[0]), "+f"(c[1]), "+f"(c[2]), "+f"(c[3])
        : "r"(a[0]), "r"(a[1]), "r"(a[2]), "r"(a[3]), "r"(b0), "r"(b1));
}
__device__ __forceinline__ void merge2(float& m1, int& i1, float& m2, int& i2,
                                       float b1, int bi1, float b2, int bi2) {
    if (b1 < m1 || (b1 == m1 && bi1 < i1)) {
        float n2; int nj2;
        if (m1 < b2 || (m1 == b2 && i1 < bi2)) { n2 = m1; nj2 = i1; } else { n2 = b2; nj2 = bi2; }
        m1 = b1; i1 = bi1; m2 = n2; i2 = nj2;
    } else if (b1 < m2 || (b1 == m2 && bi1 < i2)) {
        m2 = b1; i2 = bi1;
    }
}

// ---------------- prep: codebook column norms
__global__ void cnorm_kernel(const float* __restrict__ cb) {
    __shared__ float s[8][32];
    int c = threadIdx.x & 31, ds = threadIdx.x >> 5;
    float sum = 0.f;
    #pragma unroll
    for (int k = 0; k < 32; ++k) {
        float v = cb[(size_t)(ds * 32 + k) * KC + blockIdx.x * 32 + c];
        sum = fmaf(v, v, sum);
    }
    s[ds][c] = sum;
    __syncthreads();
    if (threadIdx.x < 32) {
        float t = 0.f;
        #pragma unroll
        for (int i = 0; i < 8; ++i) t += s[i][threadIdx.x];
        g_cnorm[blockIdx.x * 32 + threadIdx.x] = t;
    }
}

// ---------------- prep: transpose cb -> cbT[n][d]
__global__ void tr_kernel(const float* __restrict__ cb) {
    __shared__ float t[32][33];
    int n0 = blockIdx.x * 32, d0 = blockIdx.y * 32;
    int tx = threadIdx.x, ty = threadIdx.y;
    #pragma unroll
    for (int j = 0; j < 4; ++j) t[ty + j * 8][tx] = cb[(size_t)(d0 + ty + j * 8) * KC + n0 + tx];
    __syncthreads();
    #pragma unroll
    for (int j = 0; j < 4; ++j) g_cbT[(size_t)(n0 + ty + j * 8) * DIM + d0 + tx] = t[tx][ty + j * 8];
}

// ---------------- prep: fp16 split B' [n][k'] n-major
__global__ void split_kernel(const float* __restrict__ cb) {
    int id = blockIdx.x * 256 + threadIdx.x;
    int n = id & 1023, k = id >> 10;
    float v = cb[(size_t)k * KC + n];
    __half hi = __float2half_rn(v);
    __half lo = __float2half_rn(v - __half2float(hi));
    size_t base = (size_t)n * KP;
    g_bsplit[base + k] = hi;
    g_bsplit[base + 256 + k] = lo;
    g_bsplit[base + 512 + k] = hi;
}

// ---------------- main fused kernel (grid 512, block 512 = 16 warps)
__global__ __launch_bounds__(NT, 1)
void vq_main(const float* __restrict__ x, const float* __restrict__ cb,
             float* __restrict__ qout, float* __restrict__ scout) {
    extern __shared__ char smem[];
    const uint32_t su = (uint32_t)__cvta_generic_to_shared(smem);
    __half* As = (__half*)(smem + OFF_A);
    float* CN = (float*)(smem + OFF_CN);
    float* XN = (float*)(smem + OFF_XN);
    const int tid = threadIdx.x, w = tid >> 5, l = tid & 31;
    const int mw = w & 3, nw = w >> 2;          // 4 m-warps x 4 n-warps
    const int m0 = mw * 32, ncol0 = nw * 64;
    const int row0 = blockIdx.x * MR;

    // kick B chunk 0: 256 n-rows x 8 float4 of data = 2048 float4 (rows padded to 9 in smem)
    #pragma unroll
    for (int i = 0; i < 4; ++i) {
        int e = tid + i * NT;                // 0..2047
        int n = e >> 3, seg = e & 7;
        cpa16(su + OFF_B0 + (uint32_t)(n * RS_B * 2 + seg * 16),
              (const char*)g_bsplit + ((size_t)n * KP + seg * 8) * 2);
    }
    asm volatile("cp.async.commit_group;\n");

    // A split: x[128][256] f32 -> As hi (cols 0-255), lo (cols 256-511)
    {
        const float4* xs = (const float4*)(x + (size_t)row0 * DIM);
        #pragma unroll
        for (int i = 0; i < 16; ++i) {
            int e = tid + i * NT, row = e >> 6, k4 = (e & 63) * 4;
            float4 v = xs[e];
            __half h0 = __float2half_rn(v.x), h1 = __float2half_rn(v.y);
            __half h2 = __float2half_rn(v.z), h3 = __float2half_rn(v.w);
            __half* ap = As + row * RS_A + k4;
            *(__half2*)(ap)     = __halves2half2(h0, h1);
            *(__half2*)(ap + 2) = __halves2half2(h2, h3);
            *(__half2*)(ap + 256)     = __floats2half2_rn(v.x - __half2float(h0), v.y - __half2float(h1));
            *(__half2*)(ap + 256 + 2) = __floats2half2_rn(v.z - __half2float(h2), v.w - __half2float(h3));
        }
    }
    // XN: warp w -> rows 8w..8w+7
    #pragma unroll
    for (int r = 0; r < 8; ++r) {
        int row = w * 8 + r;
        const float4* xr = (const float4*)(x + (size_t)(row0 + row) * DIM);
        float4 a = xr[l * 2], b = xr[l * 2 + 1];
        float s = a.x * a.x + a.y * a.y + a.z * a.z + a.w * a.w
                + b.x * b.x + b.y * b.y + b.z * b.z + b.w * b.w;
        #pragma unroll
        for (int o = 16; o; o >>= 1) s += __shfl_xor_sync(~0u, s, o);
        if (l == 0) XN[row] = s;
    }
    CN[tid] = g_cnorm[tid];
    CN[tid + NT] = g_cnorm[tid + NT];
    __syncthreads();

    float acc[2][8][4];
    float rsum[4], tm1[4], tm2[4]; int ti1[4], ti2[4];
    #pragma unroll
    for (int q = 0; q < 4; ++q) { rsum[q] = 0.f; tm1[q] = 3.4e38f; tm2[q] = 3.4e38f; ti1[q] = 0; ti2[q] = 0; }

    // per-lane ldmatrix address components
    const uint32_t a_lane = su + OFF_A + (uint32_t)(((m0 + (l & 15)) * RS_A + ((l >> 4) << 3)) * 2);
    const uint32_t b_lane_off = (uint32_t)(((ncol0 + (l & 7) + ((l >> 4) << 3)) * RS_B + (l & 8)) * 2);

    for (int gg = 0; gg < NCHG; ++gg) {
        const int nt = gg / 12, c = gg % 12;
        if (c == 0) {
            #pragma unroll
            for (int mt = 0; mt < 2; ++mt)
                #pragma unroll
                for (int nf = 0; nf < 8; ++nf)
                    #pragma unroll
                    for (int j = 0; j < 4; ++j) acc[mt][nf][j] = 0.f;
        }
        if (gg + 1 < NCHG) {
            int nt2 = (gg + 1) / 12, c2 = (gg + 1) % 12;
            uint32_t dbuf = su + (((gg + 1) & 1) ? OFF_B1 : OFF_B0);
            #pragma unroll
            for (int i = 0; i < 4; ++i) {
                int e = tid + i * NT;            // 0..2047
                int n = e >> 3, seg = e & 7;
                cpa16(dbuf + (uint32_t)(n * RS_B * 2 + seg * 16),
                      (const char*)g_bsplit + ((size_t)(nt2 * 256 + n) * KP + c2 * CH + seg * 8) * 2);
            }
            asm volatile("cp.async.commit_group;\n");
            asm volatile("cp.async.wait_group 1;\n");
        } else {
            asm volatile("cp.async.wait_group 0;\n");
        }
        __syncthreads();

        const uint32_t bs_su = su + ((gg & 1) ? OFF_B1 : OFF_B0) + b_lane_off;
        const int acol0 = ((c >> 2) == 2 ? 256 : 0) + (c & 3) * CH;
        #pragma unroll
        for (int ks = 0; ks < 4; ++ks) {
            uint32_t a[2][4];
            uint32_t aaddr = a_lane + (uint32_t)((acol0 + ks * 16) * 2);
            ldm4(a[0], aaddr);
            ldm4(a[1], aaddr + 16 * RS_A * 2);
            #pragma unroll
            for (int np = 0; np < 4; ++np) {
                uint32_t b[4];
                ldm4(b, bs_su + (uint32_t)((np * 16 * RS_B + ks * 16) * 2));
                mma16816(acc[0][2 * np],     a[0], b[0], b[1]);
                mma16816(acc[1][2 * np],     a[1], b[0], b[1]);
                mma16816(acc[0][2 * np + 1], a[0], b[2], b[3]);
                mma16816(acc[1][2 * np + 1], a[1], b[2], b[3]);
            }
        }
        __syncthreads();

        if (c == 11) {   // ntile complete -> epilogue from fragments
            #pragma unroll
            for (int mt = 0; mt < 2; ++mt)
            #pragma unroll
            for (int t = 0; t < 2; ++t) {
                const int q = mt * 2 + t;
                const int row_l = m0 + mt * 16 + 8 * t + (l >> 2);
                const float xnr = XN[row_l];
                float* srow = scout + (size_t)(row0 + row_l) * KC;
                float m1 = tm1[q], m2 = tm2[q]; int i1 = ti1[q], i2 = ti2[q];
                float Ls = 0.f;
                #pragma unroll
                for (int h = 0; h < 2; ++h) {     // nf batches of 4 -> 8 dists
                    float p[8];
                    #pragma unroll
                    for (int j = 0; j < 4; ++j) {
                        int nf = h * 4 + j;
                        int gc = nt * 256 + ncol0 + nf * 8 + 2 * (l & 3);
                        float d0 = fmaf(-2.f, acc[mt][nf][t * 2],     xnr + CN[gc]);
                        float d1 = fmaf(-2.f, acc[mt][nf][t * 2 + 1], xnr + CN[gc + 1]);
                        p[2 * j] = d0; p[2 * j + 1] = d1;
                        if (d0 < m1)      { m2 = m1; i2 = i1; m1 = d0; i1 = gc; }
                        else if (d0 < m2) { m2 = d0; i2 = gc; }
                        if (d1 < m1)      { m2 = m1; i2 = i1; m1 = d1; i1 = gc + 1; }
                        else if (d1 < m2) { m2 = d1; i2 = gc + 1; }
                    }
                    float pa = p[0] * p[1], pb = p[2] * p[3], pc = p[4] * p[5], pd = p[6] * p[7];
                    float pab = pa * pb, pcd = pc * pd;
                    float R = frcp(pab * pcd);
                    float rab = pcd * R, rcd = pab * R;
                    float ra = pb * rab, rb = pa * rab, rc = pd * rcd, rd = pc * rcd;
                    float v0 = p[1] * ra, v1 = p[0] * ra, v2 = p[3] * rb, v3 = p[2] * rb;
                    float v4 = p[5] * rc, v5 = p[4] * rc, v6 = p[7] * rd, v7 = p[6] * rd;
                    v0 *= v0; v1 *= v1; v2 *= v2; v3 *= v3;
                    v4 *= v4; v5 *= v5; v6 *= v6; v7 *= v7;
                    Ls += ((v0 + v1) + (v2 + v3)) + ((v4 + v5) + (v6 + v7));
                    int gc0 = nt * 256 + ncol0 + h * 32 + 2 * (l & 3);
                    *(float2*)(srow + gc0)      = make_float2(v0, v1);
                    *(float2*)(srow + gc0 + 8)  = make_float2(v2, v3);
                    *(float2*)(srow + gc0 + 16) = make_float2(v4, v5);
                    *(float2*)(srow + gc0 + 24) = make_float2(v6, v7);
                }
                tm1[q] = m1; tm2[q] = m2; ti1[q] = i1; ti2[q] = i2;
                rsum[q] += Ls;
            }
        }
    }

    // ---- quad-lane reduce (lanes share row across l^1, l^2) ----
    #pragma unroll
    for (int q = 0; q < 4; ++q) {
        #pragma unroll
        for (int o = 1; o <= 2; o <<= 1) {
            float om1 = __shfl_xor_sync(~0u, tm1[q], o);
            int   oi1 = __shfl_xor_sync(~0u, ti1[q], o);
            float om2 = __shfl_xor_sync(~0u, tm2[q], o);
            int   oi2 = __shfl_xor_sync(~0u, ti2[q], o);
            float os  = __shfl_xor_sync(~0u, rsum[q], o);
            rsum[q] += os;
            merge2(tm1[q], ti1[q], tm2[q], ti2[q], om1, oi1, om2, oi2);
        }
    }
    float* M1 = (float*)(smem + OFF_SM1);
    float* M2 = (float*)(smem + OFF_SM2);
    int*   I1 = (int*)(smem + OFF_SI1);
    int*   I2 = (int*)(smem + OFF_SI2);
    float* SS = (float*)(smem + OFF_SSUM);
    float* RCP = (float*)(smem + OFF_RCP);
    int* FI1 = (int*)(smem + OFF_FI1);
    int* FI2 = (int*)(smem + OFF_FI2);
    __syncthreads();
    if ((l & 3) == 0) {
        #pragma unroll
        for (int q = 0; q < 4; ++q) {
            int row = m0 + (q >> 1) * 16 + 8 * (q & 1) + (l >> 2);
            M1[nw * 128 + row] = tm1[q]; I1[nw * 128 + row] = ti1[q];
            M2[nw * 128 + row] = tm2[q]; I2[nw * 128 + row] = ti2[q];
            SS[nw * 128 + row] = rsum[q];
        }
    }
    __syncthreads();
    if (tid < 128) {
        int row = tid;
        float m1 = M1[row], m2 = M2[row]; int i1 = I1[row], i2 = I2[row];
        float S = SS[row];
        #pragma unroll
        for (int s = 1; s < 4; ++s) {
            merge2(m1, i1, m2, i2, M1[s * 128 + row], I1[s * 128 + row],
                   M2[s * 128 + row], I2[s * 128 + row]);
            S += SS[s * 128 + row];
        }
        FI1[row] = i1; FI2[row] = i2;
        RCP[row] = 1.0f / S;
    }
    __syncthreads();

    // ---- exact fp32 guard + quantized + loss (16 warps x 8 rows) ----
    float warploss = 0.f;
    #pragma unroll
    for (int rr = 0; rr < 8; ++rr) {
        int lrow = w * 8 + rr, grow = row0 + lrow;
        int i1w = FI1[lrow], i2w = FI2[lrow];
        const float4* xr = (const float4*)(x + (size_t)grow * DIM);
        float4 xa = xr[l * 2], xb = xr[l * 2 + 1];
        const float4* c1p = (const float4*)(g_cbT + (size_t)i1w * DIM);
        const float4* c2p = (const float4*)(g_cbT + (size_t)i2w * DIM);
        float4 ca = c1p[l * 2], cb4 = c1p[l * 2 + 1];
        float4 ea = c2p[l * 2], eb = c2p[l * 2 + 1];
        float d1 = xa.x * ca.x + xa.y * ca.y + xa.z * ca.z + xa.w * ca.w
                 + xb.x * cb4.x + xb.y * cb4.y + xb.z * cb4.z + xb.w * cb4.w;
        float d2 = xa.x * ea.x + xa.y * ea.y + xa.z * ea.z + xa.w * ea.w
                 + xb.x * eb.x + xb.y * eb.y + xb.z * eb.z + xb.w * eb.w;
        #pragma unroll
        for (int o = 16; o; o >>= 1) {
            d1 += __shfl_xor_sync(~0u, d1, o);
            d2 += __shfl_xor_sync(~0u, d2, o);
        }
        float xnr2 = XN[lrow];
        float D1 = fmaf(-2.f, d1, xnr2 + CN[i1w]);
        float D2 = fmaf(-2.f, d2, xnr2 + CN[i2w]);
        float4 qa, qb;
        if ((D2 < D1) || (D2 == D1 && i2w < i1w)) { qa = ea; qb = eb; }
        else { qa = ca; qb = cb4; }
        float4* qp = (float4*)(qout + (size_t)grow * DIM);
        qp[l * 2] = qa; qp[l * 2 + 1] = qb;
        float e0 = qa.x - xa.x, e1 = qa.y - xa.y, e2 = qa.z - xa.z, e3 = qa.w - xa.w;
        float e4 = qb.x - xb.x, e5 = qb.y - xb.y, e6 = qb.z - xb.z, e7 = qb.w - xb.w;
        float lp = ((e0 * e0 + e1 * e1) + (e2 * e2 + e3 * e3))
                 + ((e4 * e4 + e5 * e5) + (e6 * e6 + e7 * e7));
        #pragma unroll
        for (int o = 16; o; o >>= 1) lp += __shfl_xor_sync(~0u, lp, o);
        warploss += lp;
    }
    if (l == 0) ((float*)(smem + OFF_WL))[w] = warploss;

    // ---- in-kernel soft-count normalization (L2-hot re-read) ----
    #pragma unroll 4
    for (int i = 0; i < 64; ++i) {
        int e = tid + i * NT;            // 0..32767 float4 over 128 rows x 256
        int row = e >> 8;
        float rS = RCP[row];
        float4* p = (float4*)(scout + (size_t)(row0 + row) * KC) + (e & 255);
        float4 v = *p;
        v.x *= rS; v.y *= rS; v.z *= rS; v.w *= rS;
        *p = v;
    }

    __syncthreads();
    if (tid == 0) {
        float* wl = (float*)(smem + OFF_WL);
        float t = 0.f;
        #pragma unroll
        for (int i = 0; i < 16; ++i) t += wl[i];
        g_partials[blockIdx.x] = t;
    }
}

// ---------------- loss reduce
__global__ void finalize_kernel(float* __restrict__ lossout, int nparts, float scale) {
    __shared__ float s[256];
    float v = 0.f;
    for (int i = threadIdx.x; i < nparts; i += 256) v += g_partials[i];
    s[threadIdx.x] = v;
    __syncthreads();
    for (int o = 128; o; o >>= 1) {
        if (threadIdx.x < o) s[threadIdx.x] += s[threadIdx.x + o];
        __syncthreads();
    }
    if (threadIdx.x == 0) lossout[0] = s[0] * scale;
}

// ---------------- launch
extern "C" void kernel_launch(void* const* d_in, const int* in_sizes, int n_in,
                              void* d_out, int out_size) {
    const float* x  = (const float*)d_in[0];
    const float* cb = (const float*)d_in[1];
    int nx = in_sizes[0], nc = in_sizes[1];
    if (nx < nc) { const float* t = x; x = cb; cb = t; int ti = nx; nx = nc; nc = ti; }

    const int nrows = nx / DIM;                        // 65536
    float* out     = (float*)d_out;
    float* qout    = out;
    float* scout   = out + (size_t)nrows * DIM;
    float* lossout = scout + (size_t)nrows * KC;

    cudaFuncSetAttribute(vq_main, cudaFuncAttributeMaxDynamicSharedMemorySize, SMEMSZ);

    cnorm_kernel<<<32, 256>>>(cb);
    tr_kernel<<<dim3(32, 8), dim3(32, 8)>>>(cb);
    split_kernel<<<1024, 256>>>(cb);
    vq_main<<<nrows / MR, NT, SMEMSZ>>>(x, cb, qout, scout);
    finalize_kernel<<<1, 256>>>(lossout, nrows / MR, 1.25f / (float)nx);
}

// round 17
// speedup vs baseline: 1.5270x; 1.0502x over previous
#include <cuda_runtime.h>
#include <cuda_fp16.h>
#include <cstdint>
#include <cstddef>

#define DIM  256
#define KC   1024
#define MR   128
#define KP   512          // B' per code: 256 hi + 256 lo halves
#define CH   64           // k' per chunk
#define NCHG 32           // 4 ntiles x 8 chunks (4 bh + 4 bl)
#define RS_A 520          // halves per A row (512 data + 8 pad)
#define RS_B 72           // halves per B n-row (64 data + 8 pad)
#define NT   512          // threads (16 warps)

// smem byte offsets
#define OFF_A    0                     // 128*520*2 = 133120
#define OFF_B0   133120                // 36864
#define OFF_B1   169984                // 36864
#define OFF_CN   206848                // 4096
#define OFF_XN   210944                // 512
#define OFF_SM1  211456                // [4][128] f
#define OFF_SM2  213504
#define OFF_SI1  215552
#define OFF_SI2  217600
#define OFF_SSUM 219648
#define OFF_RCP  221696                // 128 f
#define OFF_FI1  222208                // 128 i
#define OFF_FI2  222720                // 128 i
#define OFF_WL   223232                // 16 f
#define SMEMSZ   223296

__device__ float  g_cnorm[KC];
__device__ float  g_partials[512];
__device__ float  g_cbT[KC * DIM];      // [n][d]
__device__ __half g_bsplit[KC * KP];    // [n][k']: 0-255 Bhi, 256-511 Blo

__device__ __forceinline__ void cpa16(uint32_t sdst, const void* gsrc) {
    asm volatile("cp.async.ca.shared.global [%0], [%1], 16;\n" :: "r"(sdst), "l"(gsrc));
}
__device__ __forceinline__ float frcp(float x) {
    float r; asm("rcp.approx.ftz.f32 %0, %1;" : "=f"(r) : "f"(x)); return r;
}
__device__ __forceinline__ void ldm4(uint32_t* r, uint32_t addr) {
    asm volatile("ldmatrix.sync.aligned.m8n8.x4.shared.b16 {%0,%1,%2,%3}, [%4];"
        : "=r"(r[0]), "=r"(r[1]), "=r"(r[2]), "=r"(r[3]) : "r"(addr));
}
__device__ __forceinline__ void mma16816(float* c, const uint32_t* a, uint32_t b0, uint32_t b1) {
    asm volatile(
        "mma.sync.aligned.m16n8k16.row.col.f32.f16.f16.f32 "
        "{%0,%1,%2,%3}, {%4,%5,%6,%7}, {%8,%9}, {%0,%1,%2,%3};"
        : "+f"(c[0]), "+f"(c[1]), "+f"(c[2]), "+f"(c[3])
        : "r"(a[0]), "r"(a[1]), "r"(a[2]), "r"(a[3]), "r"(b0), "r"(b1));
}
__device__ __forceinline__ void merge2(float& m1, int& i1, float& m2, int& i2,
                                       float b1, int bi1, float b2, int bi2) {
    if (b1 < m1 || (b1 == m1 && bi1 < i1)) {
        float n2; int nj2;
        if (m1 < b2 || (m1 == b2 && i1 < bi2)) { n2 = m1; nj2 = i1; } else { n2 = b2; nj2 = bi2; }
        m1 = b1; i1 = bi1; m2 = n2; i2 = nj2;
    } else if (b1 < m2 || (b1 == m2 && bi1 < i2)) {
        m2 = b1; i2 = bi1;
    }
}

// ---------------- prep: codebook column norms
__global__ void cnorm_kernel(const float* __restrict__ cb) {
    __shared__ float s[8][32];
    int c = threadIdx.x & 31, ds = threadIdx.x >> 5;
    float sum = 0.f;
    #pragma unroll
    for (int k = 0; k < 32; ++k) {
        float v = cb[(size_t)(ds * 32 + k) * KC + blockIdx.x * 32 + c];
        sum = fmaf(v, v, sum);
    }
    s[ds][c] = sum;
    __syncthreads();
    if (threadIdx.x < 32) {
        float t = 0.f;
        #pragma unroll
        for (int i = 0; i < 8; ++i) t += s[i][threadIdx.x];
        g_cnorm[blockIdx.x * 32 + threadIdx.x] = t;
    }
}

// ---------------- prep: transpose cb -> cbT[n][d]
__global__ void tr_kernel(const float* __restrict__ cb) {
    __shared__ float t[32][33];
    int n0 = blockIdx.x * 32, d0 = blockIdx.y * 32;
    int tx = threadIdx.x, ty = threadIdx.y;
    #pragma unroll
    for (int j = 0; j < 4; ++j) t[ty + j * 8][tx] = cb[(size_t)(d0 + ty + j * 8) * KC + n0 + tx];
    __syncthreads();
    #pragma unroll
    for (int j = 0; j < 4; ++j) g_cbT[(size_t)(n0 + ty + j * 8) * DIM + d0 + tx] = t[tx][ty + j * 8];
}

// ---------------- prep: fp16 split B' [n][k'] n-major (hi then lo)
__global__ void split_kernel(const float* __restrict__ cb) {
    int id = blockIdx.x * 256 + threadIdx.x;
    int n = id & 1023, k = id >> 10;
    float v = cb[(size_t)k * KC + n];
    __half hi = __float2half_rn(v);
    __half lo = __float2half_rn(v - __half2float(hi));
    size_t base = (size_t)n * KP;
    g_bsplit[base + k] = hi;
    g_bsplit[base + 256 + k] = lo;
}

// ---------------- main fused kernel (grid 512, block 512 = 16 warps)
__global__ __launch_bounds__(NT, 1)
void vq_main(const float* __restrict__ x, const float* __restrict__ cb,
             float* __restrict__ qout, float* __restrict__ scout) {
    extern __shared__ char smem[];
    const uint32_t su = (uint32_t)__cvta_generic_to_shared(smem);
    __half* As = (__half*)(smem + OFF_A);
    float* CN = (float*)(smem + OFF_CN);
    float* XN = (float*)(smem + OFF_XN);
    const int tid = threadIdx.x, w = tid >> 5, l = tid & 31;
    const int mw = w & 3, nw = w >> 2;          // 4 m-warps x 4 n-warps
    const int m0 = mw * 32, ncol0 = nw * 64;
    const int row0 = blockIdx.x * MR;

    // kick B chunk 0: 256 n-rows x 8 float4 = 2048 float4
    #pragma unroll
    for (int i = 0; i < 4; ++i) {
        int e = tid + i * NT;                // 0..2047
        int n = e >> 3, seg = e & 7;
        cpa16(su + OFF_B0 + (uint32_t)(n * RS_B * 2 + seg * 16),
              (const char*)g_bsplit + ((size_t)n * KP + seg * 8) * 2);
    }
    asm volatile("cp.async.commit_group;\n");

    // A split: x[128][256] f32 -> As hi (cols 0-255), lo (cols 256-511)
    {
        const float4* xs = (const float4*)(x + (size_t)row0 * DIM);
        #pragma unroll
        for (int i = 0; i < 16; ++i) {
            int e = tid + i * NT, row = e >> 6, k4 = (e & 63) * 4;
            float4 v = xs[e];
            __half h0 = __float2half_rn(v.x), h1 = __float2half_rn(v.y);
            __half h2 = __float2half_rn(v.z), h3 = __float2half_rn(v.w);
            __half* ap = As + row * RS_A + k4;
            *(__half2*)(ap)     = __halves2half2(h0, h1);
            *(__half2*)(ap + 2) = __halves2half2(h2, h3);
            *(__half2*)(ap + 256)     = __floats2half2_rn(v.x - __half2float(h0), v.y - __half2float(h1));
            *(__half2*)(ap + 256 + 2) = __floats2half2_rn(v.z - __half2float(h2), v.w - __half2float(h3));
        }
    }
    // XN: warp w -> rows 8w..8w+7
    #pragma unroll
    for (int r = 0; r < 8; ++r) {
        int row = w * 8 + r;
        const float4* xr = (const float4*)(x + (size_t)(row0 + row) * DIM);
        float4 a = xr[l * 2], b = xr[l * 2 + 1];
        float s = a.x * a.x + a.y * a.y + a.z * a.z + a.w * a.w
                + b.x * b.x + b.y * b.y + b.z * b.z + b.w * b.w;
        #pragma unroll
        for (int o = 16; o; o >>= 1) s += __shfl_xor_sync(~0u, s, o);
        if (l == 0) XN[row] = s;
    }
    CN[tid] = g_cnorm[tid];
    CN[tid + NT] = g_cnorm[tid + NT];
    __syncthreads();

    float acc[2][8][4];
    float rsum[4], tm1[4], tm2[4]; int ti1[4], ti2[4];
    #pragma unroll
    for (int q = 0; q < 4; ++q) { rsum[q] = 0.f; tm1[q] = 3.4e38f; tm2[q] = 3.4e38f; ti1[q] = 0; ti2[q] = 0; }

    // per-lane ldmatrix address components
    const uint32_t a_lane = su + OFF_A + (uint32_t)(((m0 + (l & 15)) * RS_A + ((l >> 4) << 3)) * 2);
    const uint32_t b_lane_off = (uint32_t)(((ncol0 + (l & 7) + ((l >> 4) << 3)) * RS_B + (l & 8)) * 2);

    for (int gg = 0; gg < NCHG; ++gg) {
        const int nt = gg >> 3, c = gg & 7;   // c 0-3: Bhi (x Ahi AND Alo), c 4-7: Blo (x Ahi)
        if (c == 0) {
            #pragma unroll
            for (int mt = 0; mt < 2; ++mt)
                #pragma unroll
                for (int nf = 0; nf < 8; ++nf)
                    #pragma unroll
                    for (int j = 0; j < 4; ++j) acc[mt][nf][j] = 0.f;
        }
        if (gg + 1 < NCHG) {
            int nt2 = (gg + 1) >> 3, c2 = (gg + 1) & 7;
            uint32_t dbuf = su + (((gg + 1) & 1) ? OFF_B1 : OFF_B0);
            #pragma unroll
            for (int i = 0; i < 4; ++i) {
                int e = tid + i * NT;            // 0..2047
                int n = e >> 3, seg = e & 7;
                // uniform source offset: c2*64 covers both hi (0..255) and lo (256..511) regions
                cpa16(dbuf + (uint32_t)(n * RS_B * 2 + seg * 16),
                      (const char*)g_bsplit + ((size_t)(nt2 * 256 + n) * KP + c2 * CH + seg * 8) * 2);
            }
            asm volatile("cp.async.commit_group;\n");
            asm volatile("cp.async.wait_group 1;\n");
        } else {
            asm volatile("cp.async.wait_group 0;\n");
        }
        __syncthreads();

        const uint32_t bs_su = su + ((gg & 1) ? OFF_B1 : OFF_B0) + b_lane_off;
        const int kc = c & 3;
        if (c < 4) {
            // Bhi chunk: acc += Ahi*Bhi + Alo*Bhi   (A-hi at col kc*64, A-lo at col 256+kc*64)
            #pragma unroll
            for (int ks = 0; ks < 4; ++ks) {
                uint32_t ah[2][4], al[2][4];
                uint32_t aaddr = a_lane + (uint32_t)((kc * CH + ks * 16) * 2);
                ldm4(ah[0], aaddr);
                ldm4(ah[1], aaddr + 16 * RS_A * 2);
                ldm4(al[0], aaddr + 256 * 2);
                ldm4(al[1], aaddr + 256 * 2 + 16 * RS_A * 2);
                #pragma unroll
                for (int np = 0; np < 4; ++np) {
                    uint32_t b[4];
                    ldm4(b, bs_su + (uint32_t)((np * 16 * RS_B + ks * 16) * 2));
                    mma16816(acc[0][2 * np],     ah[0], b[0], b[1]);
                    mma16816(acc[1][2 * np],     ah[1], b[0], b[1]);
                    mma16816(acc[0][2 * np + 1], ah[0], b[2], b[3]);
                    mma16816(acc[1][2 * np + 1], ah[1], b[2], b[3]);
                    mma16816(acc[0][2 * np],     al[0], b[0], b[1]);
                    mma16816(acc[1][2 * np],     al[1], b[0], b[1]);
                    mma16816(acc[0][2 * np + 1], al[0], b[2], b[3]);
                    mma16816(acc[1][2 * np + 1], al[1], b[2], b[3]);
                }
            }
        } else {
            // Blo chunk: acc += Ahi*Blo
            #pragma unroll
            for (int ks = 0; ks < 4; ++ks) {
                uint32_t ah[2][4];
                uint32_t aaddr = a_lane + (uint32_t)((kc * CH + ks * 16) * 2);
                ldm4(ah[0], aaddr);
                ldm4(ah[1], aaddr + 16 * RS_A * 2);
                #pragma unroll
                for (int np = 0; np < 4; ++np) {
                    uint32_t b[4];
                    ldm4(b, bs_su + (uint32_t)((np * 16 * RS_B + ks * 16) * 2));
                    mma16816(acc[0][2 * np],     ah[0], b[0], b[1]);
                    mma16816(acc[1][2 * np],     ah[1], b[0], b[1]);
                    mma16816(acc[0][2 * np + 1], ah[0], b[2], b[3]);
                    mma16816(acc[1][2 * np + 1], ah[1], b[2], b[3]);
                }
            }
        }
        __syncthreads();

        if (c == 7) {   // ntile complete -> epilogue from fragments
            #pragma unroll
            for (int mt = 0; mt < 2; ++mt)
            #pragma unroll
            for (int t = 0; t < 2; ++t) {
                const int q = mt * 2 + t;
                const int row_l = m0 + mt * 16 + 8 * t + (l >> 2);
                const float xnr = XN[row_l];
                float* srow = scout + (size_t)(row0 + row_l) * KC;
                float m1 = tm1[q], m2 = tm2[q]; int i1 = ti1[q], i2 = ti2[q];
                float Ls = 0.f;
                #pragma unroll
                for (int h = 0; h < 2; ++h) {     // nf batches of 4 -> 8 dists
                    float p[8];
                    #pragma unroll
                    for (int j = 0; j < 4; ++j) {
                        int nf = h * 4 + j;
                        int gc = nt * 256 + ncol0 + nf * 8 + 2 * (l & 3);
                        float d0 = fmaf(-2.f, acc[mt][nf][t * 2],     xnr + CN[gc]);
                        float d1 = fmaf(-2.f, acc[mt][nf][t * 2 + 1], xnr + CN[gc + 1]);
                        p[2 * j] = d0; p[2 * j + 1] = d1;
                        if (d0 < m1)      { m2 = m1; i2 = i1; m1 = d0; i1 = gc; }
                        else if (d0 < m2) { m2 = d0; i2 = gc; }
                        if (d1 < m1)      { m2 = m1; i2 = i1; m1 = d1; i1 = gc + 1; }
                        else if (d1 < m2) { m2 = d1; i2 = gc + 1; }
                    }
                    float pa = p[0] * p[1], pb = p[2] * p[3], pc = p[4] * p[5], pd = p[6] * p[7];
                    float pab = pa * pb, pcd = pc * pd;
                    float R = frcp(pab * pcd);
                    float rab = pcd * R, rcd = pab * R;
                    float ra = pb * rab, rb = pa * rab, rc = pd * rcd, rd = pc * rcd;
                    float v0 = p[1] * ra, v1 = p[0] * ra, v2 = p[3] * rb, v3 = p[2] * rb;
                    float v4 = p[5] * rc, v5 = p[4] * rc, v6 = p[7] * rd, v7 = p[6] * rd;
                    v0 *= v0; v1 *= v1; v2 *= v2; v3 *= v3;
                    v4 *= v4; v5 *= v5; v6 *= v6; v7 *= v7;
                    Ls += ((v0 + v1) + (v2 + v3)) + ((v4 + v5) + (v6 + v7));
                    int gc0 = nt * 256 + ncol0 + h * 32 + 2 * (l & 3);
                    *(float2*)(srow + gc0)      = make_float2(v0, v1);
                    *(float2*)(srow + gc0 + 8)  = make_float2(v2, v3);
                    *(float2*)(srow + gc0 + 16) = make_float2(v4, v5);
                    *(float2*)(srow + gc0 + 24) = make_float2(v6, v7);
                }
                tm1[q] = m1; tm2[q] = m2; ti1[q] = i1; ti2[q] = i2;
                rsum[q] += Ls;
            }
        }
    }

    // ---- quad-lane reduce (lanes share row across l^1, l^2) ----
    #pragma unroll
    for (int q = 0; q < 4; ++q) {
        #pragma unroll
        for (int o = 1; o <= 2; o <<= 1) {
            float om1 = __shfl_xor_sync(~0u, tm1[q], o);
            int   oi1 = __shfl_xor_sync(~0u, ti1[q], o);
            float om2 = __shfl_xor_sync(~0u, tm2[q], o);
            int   oi2 = __shfl_xor_sync(~0u, ti2[q], o);
            float os  = __shfl_xor_sync(~0u, rsum[q], o);
            rsum[q] += os;
            merge2(tm1[q], ti1[q], tm2[q], ti2[q], om1, oi1, om2, oi2);
        }
    }
    float* M1 = (float*)(smem + OFF_SM1);
    float* M2 = (float*)(smem + OFF_SM2);
    int*   I1 = (int*)(smem + OFF_SI1);
    int*   I2 = (int*)(smem + OFF_SI2);
    float* SS = (float*)(smem + OFF_SSUM);
    float* RCP = (float*)(smem + OFF_RCP);
    int* FI1 = (int*)(smem + OFF_FI1);
    int* FI2 = (int*)(smem + OFF_FI2);
    __syncthreads();
    if ((l & 3) == 0) {
        #pragma unroll
        for (int q = 0; q < 4; ++q) {
            int row = m0 + (q >> 1) * 16 + 8 * (q & 1) + (l >> 2);
            M1[nw * 128 + row] = tm1[q]; I1[nw * 128 + row] = ti1[q];
            M2[nw * 128 + row] = tm2[q]; I2[nw * 128 + row] = ti2[q];
            SS[nw * 128 + row] = rsum[q];
        }
    }
    __syncthreads();
    if (tid < 128) {
        int row = tid;
        float m1 = M1[row], m2 = M2[row]; int i1 = I1[row], i2 = I2[row];
        float S = SS[row];
        #pragma unroll
        for (int s = 1; s < 4; ++s) {
            merge2(m1, i1, m2, i2, M1[s * 128 + row], I1[s * 128 + row],
                   M2[s * 128 + row], I2[s * 128 + row]);
            S += SS[s * 128 + row];
        }
        FI1[row] = i1; FI2[row] = i2;
        RCP[row] = 1.0f / S;
    }
    __syncthreads();

    // ---- exact fp32 guard + quantized + loss (16 warps x 8 rows) ----
    float warploss = 0.f;
    #pragma unroll
    for (int rr = 0; rr < 8; ++rr) {
        int lrow = w * 8 + rr, grow = row0 + lrow;
        int i1w = FI1[lrow], i2w = FI2[lrow];
        const float4* xr = (const float4*)(x + (size_t)grow * DIM);
        float4 xa = xr[l * 2], xb = xr[l * 2 + 1];
        const float4* c1p = (const float4*)(g_cbT + (size_t)i1w * DIM);
        const float4* c2p = (const float4*)(g_cbT + (size_t)i2w * DIM);
        float4 ca = c1p[l * 2], cb4 = c1p[l * 2 + 1];
        float4 ea = c2p[l * 2], eb = c2p[l * 2 + 1];
        float d1 = xa.x * ca.x + xa.y * ca.y + xa.z * ca.z + xa.w * ca.w
                 + xb.x * cb4.x + xb.y * cb4.y + xb.z * cb4.z + xb.w * cb4.w;
        float d2 = xa.x * ea.x + xa.y * ea.y + xa.z * ea.z + xa.w * ea.w
                 + xb.x * eb.x + xb.y * eb.y + xb.z * eb.z + xb.w * eb.w;
        #pragma unroll
        for (int o = 16; o; o >>= 1) {
            d1 += __shfl_xor_sync(~0u, d1, o);
            d2 += __shfl_xor_sync(~0u, d2, o);
        }
        float xnr2 = XN[lrow];
        float D1 = fmaf(-2.f, d1, xnr2 + CN[i1w]);
        float D2 = fmaf(-2.f, d2, xnr2 + CN[i2w]);
        float4 qa, qb;
        if ((D2 < D1) || (D2 == D1 && i2w < i1w)) { qa = ea; qb = eb; }
        else { qa = ca; qb = cb4; }
        float4* qp = (float4*)(qout + (size_t)grow * DIM);
        qp[l * 2] = qa; qp[l * 2 + 1] = qb;
        float e0 = qa.x - xa.x, e1 = qa.y - xa.y, e2 = qa.z - xa.z, e3 = qa.w - xa.w;
        float e4 = qb.x - xb.x, e5 = qb.y - xb.y, e6 = qb.z - xb.z, e7 = qb.w - xb.w;
        float lp = ((e0 * e0 + e1 * e1) + (e2 * e2 + e3 * e3))
                 + ((e4 * e4 + e5 * e5) + (e6 * e6 + e7 * e7));
        #pragma unroll
        for (int o = 16; o; o >>= 1) lp += __shfl_xor_sync(~0u, lp, o);
        warploss += lp;
    }
    if (l == 0) ((float*)(smem + OFF_WL))[w] = warploss;

    // ---- in-kernel soft-count normalization (L2-hot re-read) ----
    #pragma unroll 4
    for (int i = 0; i < 64; ++i) {
        int e = tid + i * NT;            // 0..32767 float4 over 128 rows x 256
        int row = e >> 8;
        float rS = RCP[row];
        float4* p = (float4*)(scout + (size_t)(row0 + row) * KC) + (e & 255);
        float4 v = *p;
        v.x *= rS; v.y *= rS; v.z *= rS; v.w *= rS;
        *p = v;
    }

    __syncthreads();
    if (tid == 0) {
        float* wl = (float*)(smem + OFF_WL);
        float t = 0.f;
        #pragma unroll
        for (int i = 0; i < 16; ++i) t += wl[i];
        g_partials[blockIdx.x] = t;
    }
}

// ---------------- loss reduce
__global__ void finalize_kernel(float* __restrict__ lossout, int nparts, float scale) {
    __shared__ float s[256];
    float v = 0.f;
    for (int i = threadIdx.x; i < nparts; i += 256) v += g_partials[i];
    s[threadIdx.x] = v;
    __syncthreads();
    for (int o = 128; o; o >>= 1) {
        if (threadIdx.x < o) s[threadIdx.x] += s[threadIdx.x + o];
        __syncthreads();
    }
    if (threadIdx.x == 0) lossout[0] = s[0] * scale;
}

// ---------------- launch
extern "C" void kernel_launch(void* const* d_in, const int* in_sizes, int n_in,
                              void* d_out, int out_size) {
    const float* x  = (const float*)d_in[0];
    const float* cb = (const float*)d_in[1];
    int nx = in_sizes[0], nc = in_sizes[1];
    if (nx < nc) { const float* t = x; x = cb; cb = t; int ti = nx; nx = nc; nc = ti; }

    const int nrows = nx / DIM;                        // 65536
    float* out     = (float*)d_out;
    float* qout    = out;
    float* scout   = out + (size_t)nrows * DIM;
    float* lossout = scout + (size_t)nrows * KC;

    cudaFuncSetAttribute(vq_main, cudaFuncAttributeMaxDynamicSharedMemorySize, SMEMSZ);

    cnorm_kernel<<<32, 256>>>(cb);
    tr_kernel<<<dim3(32, 8), dim3(32, 8)>>>(cb);
    split_kernel<<<1024, 256>>>(cb);
    vq_main<<<nrows / MR, NT, SMEMSZ>>>(x, cb, qout, scout);
    finalize_kernel<<<1, 256>>>(lossout, nrows / MR, 1.25f / (float)nx);
}